// round 17
// baseline (speedup 1.0000x reference)
#include <cuda_runtime.h>
#include <cstddef>

#define T_STEPS 8192
#define NRES    2048
#define DIN     64
#define DOUT    64
#define GBLK    128          // CTAs; 16 rows each (RF-forced)
#define TPB     256
#define LEAK    0.3f
#define NOISE_L 0.01f
#define TILE_T  128

// ---------------- scratch (device globals: allocation-free) ----------------
__device__ float    g_drive [T_STEPS * NRES];   // 64 MB
__device__ float    g_states[T_STEPS * NRES];   // 64 MB
__device__ float    g_sbuf  [2][NRES];          // double-buffered reservoir state
__device__ unsigned g_ctr;                      // monotonic barrier counter

// ---------------- kernel 0: reset barrier + state (determinism) -------------
__global__ void init_kernel() {
    int i = blockIdx.x * blockDim.x + threadIdx.x;
    if (i < NRES) { g_sbuf[0][i] = 0.f; g_sbuf[1][i] = 0.f; }
    if (i == 0) g_ctr = 0u;
}

// ---------------- kernel 1: drive = u @ W_in^T + 0.01*noise -----------------
// Each thread owns TWO n-columns; 128-t tiles staged in smem.
__global__ void __launch_bounds__(256) drive_kernel(const float* __restrict__ u,
                                                    const float* __restrict__ noise,
                                                    const float* __restrict__ W_in) {
    __shared__ float4 u_sh[TILE_T * (DIN / 4)];   // 32 KB
    const int tid = threadIdx.x;
    const int na  = blockIdx.x * 512 + tid;
    const int nb  = na + 256;
    const int t0  = blockIdx.y * TILE_T;

    float4 wa[DIN / 4], wb[DIN / 4];
    const float4* Wv = reinterpret_cast<const float4*>(W_in);
    #pragma unroll
    for (int j = 0; j < DIN / 4; j++) {
        wa[j] = Wv[(size_t)na * (DIN / 4) + j];
        wb[j] = Wv[(size_t)nb * (DIN / 4) + j];
    }

    const float4* uv = reinterpret_cast<const float4*>(u + (size_t)t0 * DIN);
    for (int i = tid; i < TILE_T * (DIN / 4); i += 256) u_sh[i] = uv[i];
    __syncthreads();

    for (int t = 0; t < TILE_T; t++) {
        float accA = 0.f, accB = 0.f;
        #pragma unroll
        for (int j = 0; j < DIN / 4; j++) {
            float4 uu = u_sh[t * (DIN / 4) + j];
            accA += wa[j].x * uu.x + wa[j].y * uu.y + wa[j].z * uu.z + wa[j].w * uu.w;
            accB += wb[j].x * uu.x + wb[j].y * uu.y + wb[j].z * uu.z + wb[j].w * uu.w;
        }
        size_t base = (size_t)(t0 + t) * NRES;
        g_drive[base + na] = accA + NOISE_L * noise[base + na];
        g_drive[base + nb] = accB + NOISE_L * noise[base + nb];
    }
}

// ---------------- kernel 2: persistent reservoir (R12 plateau + MLP-4 poll) -
// Split-K, warp-private staging, broadcast-LDS f32x2 FMAs, warp-0 tail,
// 2 CTA barriers/step, single monotonic counter, release-red arrival,
// 1 parked spinner per CTA. Sole change: spin polls with 4 RELAXED loads in
// flight (plain reads don't serialize; ld.acquire does) -> poll period ~70cy.
// Visibility: red.release orders the 64B publish into L2 before the counter
// increment; consumers read state only via __ldcg (L2-direct), issued after
// spin-exit + bar D (control dependence). Same physical argument as the
// fence-free tagged exchanges validated in R4-R6.
__global__ void __launch_bounds__(TPB, 1) reservoir_kernel(const float* __restrict__ W) {
    __shared__ float s_sh[8][272];            // per-warp slab: 2x(128 data + 8 pad)
    __shared__ float red_sh[2][8][17];        // parity-buffered warp partials

    const int tid  = threadIdx.x;
    const int cta  = blockIdx.x;
    const int warp = tid >> 5;
    const int lane = tid & 31;
    const int row  = lane & 15;
    const int half = lane >> 4;
    const int grow = cta * 16 + row;

    const int c0 = warp * 256 + half * 128;
    const float4* Wv = reinterpret_cast<const float4*>(W + (size_t)grow * NRES + c0);
    unsigned long long wp[64];
    #pragma unroll
    for (int k = 0; k < 32; k++) {
        float4 a = Wv[k];
        wp[2*k]   = ((unsigned long long)__float_as_uint(a.y) << 32) | __float_as_uint(a.x);
        wp[2*k+1] = ((unsigned long long)__float_as_uint(a.w) << 32) | __float_as_uint(a.z);
    }

    const bool tail = (warp == 0) && (lane < 16);
    float sp   = 0.f;
    float dcur = 0.f;
    if (tail) dcur = g_drive[grow];

    float4* slab4 = reinterpret_cast<float4*>(s_sh[warp]);
    const int rdbase = 34 * half;

    #pragma unroll 1
    for (int t = 0; t < T_STEPS; t++) {
        // ---- warp-private stage: 2 coalesced 512B LDGs, STS, syncwarp ------
        const float4* sg = reinterpret_cast<const float4*>(g_sbuf[t & 1]) + warp * 64;
        float4 vA = __ldcg(sg + lane);
        float4 vB = __ldcg(sg + 32 + lane);
        slab4[lane]      = vA;
        slab4[34 + lane] = vB;
        __syncwarp();

        // ---- broadcast-LDS split-K partials (4 f32x2 chains) ---------------
        unsigned long long aA = 0, aB = 0, aC = 0, aD = 0;
        #pragma unroll
        for (int k = 0; k < 32; k += 2) {
            float4 sv  = slab4[rdbase + k];
            float4 sv2 = slab4[rdbase + k + 1];
            asm("{\n\t"
                ".reg .b64 p0, p1, p2, p3;\n\t"
                "mov.b64 p0, {%4, %5};\n\t"
                "mov.b64 p1, {%6, %7};\n\t"
                "mov.b64 p2, {%8, %9};\n\t"
                "mov.b64 p3, {%10, %11};\n\t"
                "fma.rn.f32x2 %0, %12, p0, %0;\n\t"
                "fma.rn.f32x2 %1, %13, p1, %1;\n\t"
                "fma.rn.f32x2 %2, %14, p2, %2;\n\t"
                "fma.rn.f32x2 %3, %15, p3, %3;\n\t"
                "}"
                : "+l"(aA), "+l"(aB), "+l"(aC), "+l"(aD)
                : "f"(sv.x), "f"(sv.y), "f"(sv.z), "f"(sv.w),
                  "f"(sv2.x), "f"(sv2.y), "f"(sv2.z), "f"(sv2.w),
                  "l"(wp[2*k]), "l"(wp[2*k+1]), "l"(wp[2*k+2]), "l"(wp[2*k+3]));
        }
        float e0, o0, e1, o1;
        asm("{\n\t.reg .b64 r0;\n\tadd.rn.f32x2 r0, %2, %3;\n\tmov.b64 {%0, %1}, r0;\n\t}"
            : "=f"(e0), "=f"(o0) : "l"(aA), "l"(aB));
        asm("{\n\t.reg .b64 r1;\n\tadd.rn.f32x2 r1, %2, %3;\n\tmov.b64 {%0, %1}, r1;\n\t}"
            : "=f"(e1), "=f"(o1) : "l"(aC), "l"(aD));
        float part = (e0 + o0) + (e1 + o1);
        part += __shfl_xor_sync(0xffffffffu, part, 16);

        const int par = t & 1;
        if (lane < 16) red_sh[par][warp][row] = part;
        __syncthreads();                                 // bar B

        // ---- tail: warp 0's 16 lanes tree-reduce 8 warps, update, publish --
        if (tail) {
            float p0 = red_sh[par][0][row], p1 = red_sh[par][1][row];
            float p2 = red_sh[par][2][row], p3 = red_sh[par][3][row];
            float p4 = red_sh[par][4][row], p5 = red_sh[par][5][row];
            float p6 = red_sh[par][6][row], p7 = red_sh[par][7][row];
            float sum = dcur + (((p0 + p1) + (p2 + p3)) + ((p4 + p5) + (p6 + p7)));
            float z  = __expf(2.f * sum);                // tanh = 1 - 2/(e^2x+1)
            float th = 1.f - __fdividef(2.f, z + 1.f);
            float ns = (1.f - LEAK) * sp + LEAK * th;
            sp = ns;
            g_sbuf[(t + 1) & 1][grow] = ns;              // coalesced 64B publish
            __stcs(&g_states[(size_t)t * NRES + grow], ns);
            if (t + 1 < T_STEPS)                         // prefetch under spin
                dcur = g_drive[(size_t)(t + 1) * NRES + grow];
        }
        __syncwarp();                                    // order warp-0 publishes

        // ---- monotonic grid barrier: release-red arrival, MLP-4 spin -------
        if (tid == 0) {
            asm volatile("red.release.gpu.global.add.u32 [%0], 1;"
                         :: "l"(&g_ctr) : "memory");
            const unsigned target = (unsigned)(t + 1) * GBLK;
            unsigned c0r, c1r, c2r, c3r;
            do {                                         // 4 independent polls
                asm volatile("ld.relaxed.gpu.global.u32 %0, [%4];\n\t"
                             "ld.relaxed.gpu.global.u32 %1, [%4];\n\t"
                             "ld.relaxed.gpu.global.u32 %2, [%4];\n\t"
                             "ld.relaxed.gpu.global.u32 %3, [%4];"
                             : "=r"(c0r), "=r"(c1r), "=r"(c2r), "=r"(c3r)
                             : "l"(&g_ctr));
                c0r = max(max(c0r, c1r), max(c2r, c3r)); // counter is monotonic
            } while (c0r < target);
        }
        __syncthreads();                                 // bar D: release CTA
    }
}

// ---------------- kernel 3: out = states @ w_out^T + b_out ------------------
// v3: 32-row tiles x 256 CTAs (2x CTA-level latency hiding), float4 loads,
// pad-65 smem.
__global__ void __launch_bounds__(256) proj_kernel(const float* __restrict__ w_out,
                                                   const float* __restrict__ b_out,
                                                   float* __restrict__ out) {
    __shared__ float s_sh[32][65];            // 8.3 KB
    __shared__ float w_sh[DOUT][65];          // 16.6 KB
    const int t0  = blockIdx.x * 32;
    const int tid = threadIdx.x;
    const int tx  = tid & 15;                 // output group: 4 outs
    const int ty  = tid >> 4;                 // row group: 2 rows
    float acc[2][4] = {};

    for (int kc = 0; kc < NRES; kc += 64) {
        for (int i = tid; i < 32 * 16; i += 256) {
            int r = i >> 4, c = i & 15;
            float4 v = *reinterpret_cast<const float4*>(
                &g_states[(size_t)(t0 + r) * NRES + kc + c * 4]);
            s_sh[r][c*4+0] = v.x; s_sh[r][c*4+1] = v.y;
            s_sh[r][c*4+2] = v.z; s_sh[r][c*4+3] = v.w;
        }
        for (int i = tid; i < DOUT * 16; i += 256) {
            int o = i >> 4, c = i & 15;
            float4 v = *reinterpret_cast<const float4*>(
                &w_out[(size_t)o * NRES + kc + c * 4]);
            w_sh[o][c*4+0] = v.x; w_sh[o][c*4+1] = v.y;
            w_sh[o][c*4+2] = v.z; w_sh[o][c*4+3] = v.w;
        }
        __syncthreads();
        for (int k = 0; k < 64; k++) {
            float sv[2], wv[4];
            #pragma unroll
            for (int i = 0; i < 2; i++) sv[i] = s_sh[ty * 2 + i][k];
            #pragma unroll
            for (int j = 0; j < 4; j++) wv[j] = w_sh[tx * 4 + j][k];
            #pragma unroll
            for (int i = 0; i < 2; i++)
                #pragma unroll
                for (int j = 0; j < 4; j++)
                    acc[i][j] += sv[i] * wv[j];
        }
        __syncthreads();
    }
    #pragma unroll
    for (int i = 0; i < 2; i++)
        #pragma unroll
        for (int j = 0; j < 4; j++)
            out[(size_t)(t0 + ty * 2 + i) * DOUT + tx * 4 + j] = acc[i][j] + b_out[tx * 4 + j];
}

// ---------------- launch ----------------------------------------------------
extern "C" void kernel_launch(void* const* d_in, const int* in_sizes, int n_in,
                              void* d_out, int out_size) {
    const float* u     = (const float*)d_in[0];  // (8192, 64)
    const float* noise = (const float*)d_in[1];  // (8192, 2048)
    const float* W_in  = (const float*)d_in[2];  // (2048, 64)
    const float* W     = (const float*)d_in[3];  // (2048, 2048)
    const float* w_out = (const float*)d_in[4];  // (64, 2048)
    const float* b_out = (const float*)d_in[5];  // (64,)
    float* out = (float*)d_out;                  // (8192, 64)

    init_kernel<<<NRES / 256, 256>>>();
    drive_kernel<<<dim3(NRES / 512, T_STEPS / TILE_T), 256>>>(u, noise, W_in);
    reservoir_kernel<<<GBLK, TPB>>>(W);
    proj_kernel<<<T_STEPS / 32, 256>>>(w_out, b_out, out);
}